// round 14
// baseline (speedup 1.0000x reference)
#include <cuda_runtime.h>
#include <math.h>
#include <float.h>

#define Bn   4
#define Hn   32
#define HKV  8
#define Gn   4
#define Dn   128
#define Pn   128
#define Sn   64
#define KP   16
#define NEGV (-1000000000.0f)
#define SM_SCALE 0.08838834764831845f

// Scratch (allocation-free rule: __device__ globals)
__device__ float g_qr    [Bn*Hn*Dn];      // roped q (unscaled)
__device__ float g_scores[Bn*Hn*Pn*Sn];   // 4 MB masked score matrix
__device__ float g_stats [Bn*Hn*Pn];      // per-page max
__device__ float g_part  [Bn*Hn*KP*Dn];   // per-(head,page) partial sum(exp*V)
__device__ float g_pden  [Bn*Hn*KP];      // per-(head,page) partial denom
__device__ int   g_cnt   [Bn*Hn];         // attn arrival counters (zero-init)
__device__ int   g_flag  [Bn*HKV];        // rope-ready flags (zero-init)
__device__ int   g_done  [Bn*HKV];        // score done counters (zero-init)

// ---------------------------------------------------------------- kernel 1
// One block per (page, b*HKV): 256 threads, 8 warps x 8 tokens.
// Block p==0 of each bh ropes its 4 heads' q (one sincos per thread) into
// g_qr and releases g_flag[bh]; other blocks spin (tid 0) on the flag.
// Deadlock-free: block (0,bh) has the lowest linear index of its bh group
// and dispatch is in-order, so the roper is resident before its spinners.
// Flags/counters self-reset (128th finishing block) for graph replay.
__global__ void __launch_bounds__(256, 4)
score_kernel(const float* __restrict__ q,
             const int*   __restrict__ k_cache,
             const float* __restrict__ kv_scale,
             const int*   __restrict__ lengths,
             const int*   __restrict__ timestep)
{
    __shared__ float smax[8][Gn];

    int p   = blockIdx.x;
    int bh  = blockIdx.y;            // b*HKV + hkv
    int b   = bh >> 3, hkv = bh & 7;
    int tid = threadIdx.x;
    int w   = tid >> 5, lane = tid & 31;
    int len = max(lengths[b], 1);
    int head0 = b*Hn + hkv*Gn;

    bool masked = (p*Sn >= len);     // p==0 never masked (len >= 1)

    if (masked) {
        // fully masked page. Only page Pn-1 can ever be selected while masked.
        if (p == Pn-1 && tid < Sn) {
            #pragma unroll
            for (int g = 0; g < Gn; g++)
                g_scores[(size_t)(head0+g)*Pn*Sn + p*Sn + tid] = NEGV;
        }
        if (tid < Gn) g_stats[(head0+tid)*Pn + p] = NEGV;
    } else {
        if (p == 0) {
            // rope this bh's 4 heads: thread -> (g = tid>>6, t = tid&63)
            int g = tid >> 6, t = tid & 63;
            const float* src = q + (size_t)(head0+g)*Dn;
            float x1 = src[t], x2 = src[t+64];
            float pos = (float)(timestep[0] - 1);
            float inv = 1.0f / powf(10000.0f, (float)t * (2.0f / (float)Dn));
            float c, s;
            sincosf(pos * inv, &s, &c);
            float* dst = g_qr + (size_t)(head0+g)*Dn;
            dst[t]    = x1*c - x2*s;
            dst[t+64] = x1*s + x2*c;
            __threadfence();
            __syncthreads();
            if (tid == 0) atomicExch(&g_flag[bh], 1);
        } else {
            if (tid == 0) {
                volatile int* vf = &g_flag[bh];
                while (*vf == 0) {}
            }
            __syncthreads();
            __threadfence();
        }

        // q: lane owns dims 4*lane..4*lane+3, all 4 heads (roped, unscaled)
        float4 qr[Gn];
        #pragma unroll
        for (int g = 0; g < Gn; g++)
            qr[g] = *(const float4*)(g_qr + (size_t)(head0+g)*Dn + 4*lane);

        float sks = kv_scale[0] * SM_SCALE;

        const int4* kbase = (const int4*)(k_cache +
            ((((size_t)b*Pn + p)*Sn + w*8)*HKV + hkv)*Dn) + lane;

        // lane -> (g, t) after butterfly: g = (lane>>3)&3, t = (lane>>1)&3
        int g  = (lane >> 3) & 3;
        int tt = (lane >> 1) & 3;

        float pmax = NEGV;
        #pragma unroll
        for (int c = 0; c < 2; c++) {
            int4 kv[4];
            #pragma unroll
            for (int t = 0; t < 4; t++)
                kv[t] = kbase[(size_t)(c*4 + t) * (HKV*Dn/4)];

            float vals[16];
            #pragma unroll
            for (int i = 0; i < 16; i++) vals[i] = 0.f;

            #pragma unroll
            for (int t = 0; t < 4; t++) {
                float f0=(float)kv[t].x, f1=(float)kv[t].y,
                      f2=(float)kv[t].z, f3=(float)kv[t].w;
                #pragma unroll
                for (int gg = 0; gg < Gn; gg++)
                    vals[gg*4+t] += f0*qr[gg].x + f1*qr[gg].y
                                  + f2*qr[gg].z + f3*qr[gg].w;
            }

            // butterfly transpose-reduce; then fold duplicated lane bit 0
            #pragma unroll
            for (int st = 0; st < 4; st++) {
                int o = 16 >> st, d = 8 >> st;
                #pragma unroll
                for (int a = 0; a < 8; a++) {
                    if (a >= d) break;
                    float lo = vals[a], hi = vals[a+d];
                    float send = (lane & o) ? lo : hi;
                    float recv = __shfl_xor_sync(0xffffffffu, send, o);
                    vals[a] = ((lane & o) ? hi : lo) + recv;
                }
            }
            float v = vals[0] + __shfl_xor_sync(0xffffffffu, vals[0], 1);

            int tok = w*8 + c*4 + tt;
            bool valid = p*Sn + tok < len;
            float sc = valid ? v*sks : NEGV;
            if (!(lane & 1))
                g_scores[(size_t)(head0+g)*Pn*Sn + p*Sn + tok] = sc;
            pmax = fmaxf(pmax, sc);
        }

        // per-g page max: reduce over lane bits 4,2 (bit 1 duplicated)
        pmax = fmaxf(pmax, __shfl_xor_sync(0xffffffffu, pmax, 4));
        pmax = fmaxf(pmax, __shfl_xor_sync(0xffffffffu, pmax, 2));

        if ((lane & 7) == 0) smax[w][g] = pmax;
        __syncthreads();
        if (tid < 32) {
            // tid = g2*8 + w2
            float v = smax[tid & 7][tid >> 3];
            #pragma unroll
            for (int o = 4; o >= 1; o >>= 1)
                v = fmaxf(v, __shfl_xor_sync(0xffffffffu, v, o));
            if ((tid & 7) == 0)
                g_stats[(head0 + (tid >> 3))*Pn + p] = v;
        }
    }

    // done-count: 128th finishing block of this bh resets flag+counter
    __syncthreads();
    if (tid == 0) {
        int old = atomicAdd(&g_done[bh], 1);
        if (old == Pn-1) { g_done[bh] = 0; g_flag[bh] = 0; }
    }
}

// ---------------------------------------------------------------- kernel 2
// One block per (head, kp): 2048 blocks x 128 threads.
// EVERY warp independently derives the kp-th top page (REDUX argmax,
// jax.lax.top_k semantics incl. min-index tie-break), current score and
// softmax max -> no inter-warp sync before V loads. Weights live in lane
// registers, broadcast by shfl. Last-arriving block per head finalizes.
__device__ __forceinline__ unsigned int fkey(float f) {
    unsigned int u = __float_as_uint(f);
    return u ^ ((u & 0x80000000u) ? 0xFFFFFFFFu : 0x80000000u);
}

__global__ void attn_kernel(const float* __restrict__ q,
                            const float* __restrict__ k_cur,
                            const int*   __restrict__ v_cache,
                            const float* __restrict__ v_cur,
                            const float* __restrict__ kv_scale,
                            float* __restrict__ out,
                            float* __restrict__ out_idx, int write_idx)
{
    __shared__ float4 part[4][32];
    __shared__ float  wden[4];
    __shared__ int    s_last;

    int bid  = blockIdx.x;
    int head = bid >> 4;
    int kp   = bid & (KP-1);
    int tid  = threadIdx.x;
    int warp = tid >> 5, lane = tid & 31;
    int b = head >> 5;                 // head / Hn
    int hkv = (head & (Hn-1)) >> 2;    // (head % Hn) / Gn

    const float* st = g_stats + head*Pn;

    // ---- per-warp: topk keys (32-bit monotone floats; 0 = dead/invalid)
    unsigned int f[4];
    #pragma unroll
    for (int j = 0; j < 4; j++) {
        int idx = lane + j*32;
        f[j] = (idx < Pn-1) ? fkey(st[idx]) : 0u;
    }

    // current-token score: rope(q).rope(k) == q.k (same-position rotation)
    float4 qa = *(const float4*)(q + (size_t)head*Dn + 4*lane);
    float4 ka = *(const float4*)(k_cur + (size_t)(b*HKV + hkv)*Dn + 4*lane);
    float prod = qa.x*ka.x + qa.y*ka.y + qa.z*ka.z + qa.w*ka.w;
    #pragma unroll
    for (int o = 16; o >= 1; o >>= 1)
        prod += __shfl_xor_sync(0xffffffffu, prod, o);
    float curv = prod * SM_SCALE;

    // iterate to rank kp (rank 0 only for the forced page Pn-1)
    int iters = (kp == KP-1) ? 1 : (kp + 1);
    unsigned int sel = 0, sel0 = 0;
    for (int it = 0; it < iters; it++) {
        unsigned int local = max(max(f[0], f[1]), max(f[2], f[3]));
        unsigned int best  = __reduce_max_sync(0xffffffffu, local);
        unsigned int my = 0xFFFFFFFFu;
        #pragma unroll
        for (int j = 0; j < 4; j++)
            if (f[j] == best) my = min(my, (unsigned int)(lane + j*32));
        sel = __reduce_min_sync(0xffffffffu, my);
        if (it == 0) sel0 = sel;
        #pragma unroll
        for (int j = 0; j < 4; j++)
            if ((unsigned int)(lane + j*32) == sel) f[j] = 0u;
    }
    int page = (kp == KP-1) ? (Pn-1) : (int)sel;
    float m = fmaxf(fmaxf(st[sel0], st[Pn-1]), curv);

    if (tid == 0 && write_idx) out_idx[head*KP + kp] = (float)page;

    // ---- weights in registers: lane s2 (<16) owns token 4*s2 + warp
    float wv = 0.f;
    if (lane < 16)
        wv = __expf(g_scores[(size_t)head*Pn*Sn + page*Sn + 4*lane + warp] - m);

    // per-warp denom partial
    {
        float d = wv;
        #pragma unroll
        for (int o = 16; o >= 1; o >>= 1)
            d += __shfl_xor_sync(0xffffffffu, d, o);
        if (lane == 0) wden[warp] = d;
    }

    // ---- V accumulation: warp handles tokens s == warp (mod 4)
    const int4* vp = (const int4*)(v_cache +
        (((size_t)(b*Pn + page)*Sn)*HKV + hkv)*Dn) + lane;
    float a0=0.f, a1=0.f, a2=0.f, a3=0.f;
    #pragma unroll
    for (int s2 = 0; s2 < 16; s2++) {
        int4 vv = vp[(size_t)(s2*4 + warp) * (HKV*Dn/4)];
        float ww = __shfl_sync(0xffffffffu, wv, s2);
        a0 += ww*(float)vv.x; a1 += ww*(float)vv.y;
        a2 += ww*(float)vv.z; a3 += ww*(float)vv.w;
    }
    part[warp][lane] = make_float4(a0, a1, a2, a3);
    __syncthreads();

    {
        int lane2 = tid >> 2, comp = tid & 3;
        float acc = 0.f;
        #pragma unroll
        for (int g2 = 0; g2 < 4; g2++) {
            float4 pv = part[g2][lane2];
            acc += (comp==0) ? pv.x : (comp==1) ? pv.y : (comp==2) ? pv.z : pv.w;
        }
        g_part[((size_t)head*KP + kp)*Dn + tid] = acc;
    }
    if (tid == 0)
        g_pden[head*KP + kp] = (wden[0] + wden[1]) + (wden[2] + wden[3]);

    // arrival counter: last block of this head finalizes (deterministic sum)
    __threadfence();
    __syncthreads();
    if (tid == 0) {
        int old = atomicAdd(&g_cnt[head], 1);
        s_last = (old == KP-1) ? 1 : 0;
        if (s_last) g_cnt[head] = 0;   // reset for next graph replay
    }
    __syncthreads();
    if (!s_last) return;
    __threadfence();

    float acc = 0.f;
    const float* pp = g_part + (size_t)head*KP*Dn + tid;
    #pragma unroll
    for (int j = 0; j < KP; j++) acc += pp[j*Dn];

    float ecur = __expf(curv - m);
    float den = ecur;
    const float* dp = g_pden + head*KP;
    #pragma unroll
    for (int j = 0; j < KP; j++) den += dp[j];

    float o = acc * kv_scale[1] + ecur * v_cur[(size_t)(b*HKV + hkv)*Dn + tid];
    out[(size_t)head*Dn + tid] = o / den;
}

// ---------------------------------------------------------------- launch
extern "C" void kernel_launch(void* const* d_in, const int* in_sizes, int n_in,
                              void* d_out, int out_size)
{
    const float* q        = (const float*)d_in[0];
    const float* k        = (const float*)d_in[1];
    const float* v        = (const float*)d_in[2];
    const float* kv_scale = (const float*)d_in[3];
    const int*   k_cache  = (const int*)  d_in[4];
    const int*   v_cache  = (const int*)  d_in[5];
    const int*   lengths  = (const int*)  d_in[6];
    const int*   timestep = (const int*)  d_in[7];
    float* out = (float*)d_out;

    int write_idx = (out_size >= Bn*Hn*Dn + Bn*Hn*KP) ? 1 : 0;

    score_kernel<<<dim3(Pn, Bn*HKV), 256>>>(q, k_cache, kv_scale, lengths, timestep);
    attn_kernel<<<Bn*Hn*KP, 128>>>(q, k, v_cache, v, kv_scale, out,
                                   out + Bn*Hn*Dn, write_idx);
}

// round 15
// speedup vs baseline: 1.3457x; 1.3457x over previous
#include <cuda_runtime.h>
#include <math.h>
#include <float.h>

#define Bn   4
#define Hn   32
#define HKV  8
#define Gn   4
#define Dn   128
#define Pn   128
#define Sn   64
#define KP   16
#define NEGV (-1000000000.0f)
#define SM_SCALE 0.08838834764831845f

// Scratch (allocation-free rule: __device__ globals)
__device__ float g_qr    [Bn*Hn*Dn];      // roped q (unscaled)
__device__ float g_scores[Bn*Hn*Pn*Sn];   // 4 MB masked score matrix
__device__ float g_stats [Bn*Hn*Pn];      // per-page max
__device__ float g_part  [Bn*Hn*8*Dn];    // per-(head,block) partial sum(exp*V)
__device__ float g_pden  [Bn*Hn*8];       // per-(head,block) partial denom
__device__ int   g_cnt   [Bn*Hn];         // attn arrival counters (zero-init)

// ---------------------------------------------------------------- kernel 0
// RoPE (neox) for q only (same-position rotation preserves q.k for the
// current token, so k_cur is never roped). q loads issued before the
// timestep->powf->sincos chain to overlap DRAM latency.
__global__ void prep_kernel(const float* __restrict__ q,
                            const int*   __restrict__ timestep)
{
    int i = blockIdx.x;          // head 0..127
    int t = threadIdx.x;         // 0..63
    const float* src = q + (size_t)i*Dn;
    float x1 = src[t], x2 = src[t+64];          // issue early

    float pos = (float)(timestep[0] - 1);
    float inv = 1.0f / powf(10000.0f, (float)t * (2.0f / (float)Dn));
    float c, s;
    sincosf(pos * inv, &s, &c);

    float* dst = g_qr + (size_t)i*Dn;
    dst[t]    = x1*c - x2*s;
    dst[t+64] = x1*s + x2*c;
}

// ---------------------------------------------------------------- kernel 1
// One block per (page, b*HKV): 256 threads, 8 warps x 8 tokens.
// Lane owns dims [4*lane,4*lane+4); q pre-roped in registers.
// Two 4-token chunks; butterfly transpose-reduce of 16 vals over 32 lanes.
__global__ void __launch_bounds__(256, 4)
score_kernel(const int*   __restrict__ k_cache,
             const float* __restrict__ kv_scale,
             const int*   __restrict__ lengths)
{
    int p   = blockIdx.x;
    int bh  = blockIdx.y;            // b*HKV + hkv
    int b   = bh >> 3, hkv = bh & 7;
    int tid = threadIdx.x;
    int w   = tid >> 5, lane = tid & 31;
    int len = max(lengths[b], 1);
    int head0 = b*Hn + hkv*Gn;

    if (p*Sn >= len) {
        // fully masked page. Only page Pn-1 can ever be selected while masked.
        if (p == Pn-1 && tid < Sn) {
            #pragma unroll
            for (int g = 0; g < Gn; g++)
                g_scores[(size_t)(head0+g)*Pn*Sn + p*Sn + tid] = NEGV;
        }
        if (tid < Gn) g_stats[(head0+tid)*Pn + p] = NEGV;
        return;
    }

    // q: lane owns dims 4*lane..4*lane+3, all 4 heads (pre-roped, unscaled)
    float4 qr[Gn];
    #pragma unroll
    for (int g = 0; g < Gn; g++)
        qr[g] = *(const float4*)(g_qr + (size_t)(head0+g)*Dn + 4*lane);

    float sks = kv_scale[0] * SM_SCALE;

    const int4* kbase = (const int4*)(k_cache +
        ((((size_t)b*Pn + p)*Sn + w*8)*HKV + hkv)*Dn) + lane;

    // lane -> (g, t) after butterfly: g = (lane>>3)&3, t = (lane>>1)&3
    int g  = (lane >> 3) & 3;
    int tt = (lane >> 1) & 3;

    float pmax = NEGV;
    #pragma unroll
    for (int c = 0; c < 2; c++) {
        int4 kv[4];
        #pragma unroll
        for (int t = 0; t < 4; t++)
            kv[t] = kbase[(size_t)(c*4 + t) * (HKV*Dn/4)];

        float vals[16];
        #pragma unroll
        for (int i = 0; i < 16; i++) vals[i] = 0.f;

        #pragma unroll
        for (int t = 0; t < 4; t++) {
            float f0=(float)kv[t].x, f1=(float)kv[t].y,
                  f2=(float)kv[t].z, f3=(float)kv[t].w;
            #pragma unroll
            for (int gg = 0; gg < Gn; gg++)
                vals[gg*4+t] += f0*qr[gg].x + f1*qr[gg].y
                              + f2*qr[gg].z + f3*qr[gg].w;
        }

        // butterfly: stages (o=16,d=8) (8,4) (4,2) (2,1); then fold lane bit 0
        #pragma unroll
        for (int st = 0; st < 4; st++) {
            int o = 16 >> st, d = 8 >> st;
            #pragma unroll
            for (int a = 0; a < 8; a++) {
                if (a >= d) break;
                float lo = vals[a], hi = vals[a+d];
                float send = (lane & o) ? lo : hi;
                float recv = __shfl_xor_sync(0xffffffffu, send, o);
                vals[a] = ((lane & o) ? hi : lo) + recv;
            }
        }
        float v = vals[0] + __shfl_xor_sync(0xffffffffu, vals[0], 1);

        int tok = w*8 + c*4 + tt;
        bool valid = p*Sn + tok < len;
        float sc = valid ? v*sks : NEGV;
        if (!(lane & 1))
            g_scores[(size_t)(head0+g)*Pn*Sn + p*Sn + tok] = sc;
        pmax = fmaxf(pmax, sc);
    }

    // per-g page max: reduce over lane bits 4,2 (bit 1 already duplicated)
    pmax = fmaxf(pmax, __shfl_xor_sync(0xffffffffu, pmax, 4));
    pmax = fmaxf(pmax, __shfl_xor_sync(0xffffffffu, pmax, 2));

    __shared__ float smax[8][Gn];
    if ((lane & 7) == 0) smax[w][g] = pmax;
    __syncthreads();
    if (tid < 32) {
        // tid = g2*8 + w2
        float v = smax[tid & 7][tid >> 3];
        #pragma unroll
        for (int o = 4; o >= 1; o >>= 1)
            v = fmaxf(v, __shfl_xor_sync(0xffffffffu, v, o));
        if ((tid & 7) == 0)
            g_stats[(head0 + (tid >> 3))*Pn + p] = v;
    }
}

// ---------------------------------------------------------------- kernel 2
// One block per (head, j): 1024 blocks x 128 threads; block j handles
// ranks kp = 2j and 2j+1 (j=7: rank 14 + forced page 127).
// EVERY warp independently derives the pages (REDUX argmax, jax.lax.top_k
// semantics incl. min-index tie-break), current score and softmax max ->
// no inter-warp sync before V loads. Weights in lane registers (shfl
// broadcast). Last-arriving block per head finalizes (fixed-order sum).
__device__ __forceinline__ unsigned int fkey(float f) {
    unsigned int u = __float_as_uint(f);
    return u ^ ((u & 0x80000000u) ? 0xFFFFFFFFu : 0x80000000u);
}

__global__ void attn_kernel(const float* __restrict__ q,
                            const float* __restrict__ k_cur,
                            const int*   __restrict__ v_cache,
                            const float* __restrict__ v_cur,
                            const float* __restrict__ kv_scale,
                            float* __restrict__ out,
                            float* __restrict__ out_idx, int write_idx)
{
    __shared__ float4 part[4][32];
    __shared__ float  wden[4];
    __shared__ int    s_last;

    int bid  = blockIdx.x;
    int head = bid >> 3;
    int j    = bid & 7;
    int tid  = threadIdx.x;
    int warp = tid >> 5, lane = tid & 31;
    int b = head >> 5;                 // head / Hn
    int hkv = (head & (Hn-1)) >> 2;    // (head % Hn) / Gn

    const float* st = g_stats + head*Pn;

    // ---- per-warp: topk keys (32-bit monotone floats; 0 = dead/invalid)
    unsigned int f[4];
    #pragma unroll
    for (int jj = 0; jj < 4; jj++) {
        int idx = lane + jj*32;
        f[jj] = (idx < Pn-1) ? fkey(st[idx]) : 0u;
    }

    // current-token score: rope(q).rope(k) == q.k (same-position rotation)
    float4 qa = *(const float4*)(q + (size_t)head*Dn + 4*lane);
    float4 ka = *(const float4*)(k_cur + (size_t)(b*HKV + hkv)*Dn + 4*lane);
    float prod = qa.x*ka.x + qa.y*ka.y + qa.z*ka.z + qa.w*ka.w;
    #pragma unroll
    for (int o = 16; o >= 1; o >>= 1)
        prod += __shfl_xor_sync(0xffffffffu, prod, o);
    float curv = prod * SM_SCALE;

    // iterate to rank 2j+1 (j<7) or rank 14 (j==7)
    int iters = (j == 7) ? (KP-1) : (2*j + 2);
    unsigned int sel = 0, sel0 = 0, selA = 0;
    for (int it = 0; it < iters; it++) {
        unsigned int local = max(max(f[0], f[1]), max(f[2], f[3]));
        unsigned int best  = __reduce_max_sync(0xffffffffu, local);
        unsigned int my = 0xFFFFFFFFu;
        #pragma unroll
        for (int jj = 0; jj < 4; jj++)
            if (f[jj] == best) my = min(my, (unsigned int)(lane + jj*32));
        sel = __reduce_min_sync(0xffffffffu, my);
        if (it == 0) sel0 = sel;
        if (it == 2*j) selA = sel;
        #pragma unroll
        for (int jj = 0; jj < 4; jj++)
            if ((unsigned int)(lane + jj*32) == sel) f[jj] = 0u;
    }
    int pageA = (int)selA;                         // rank 2j (j=7: rank 14)
    int pageB = (j == 7) ? (Pn-1) : (int)sel;      // rank 2j+1 or forced 127
    float m = fmaxf(fmaxf(st[sel0], st[Pn-1]), curv);

    if (tid == 0 && write_idx) {
        out_idx[head*KP + 2*j]     = (float)pageA;
        out_idx[head*KP + 2*j + 1] = (float)pageB;
    }

    // ---- weights in registers: lane s2 (<16) owns token 4*s2 + warp
    const float* scb = g_scores + (size_t)head*Pn*Sn;
    float wv0 = 0.f, wv1 = 0.f;
    if (lane < 16) {
        wv0 = __expf(scb[pageA*Sn + 4*lane + warp] - m);
        wv1 = __expf(scb[pageB*Sn + 4*lane + warp] - m);
    }

    // per-warp denom partial (both pages)
    {
        float d = wv0 + wv1;
        #pragma unroll
        for (int o = 16; o >= 1; o >>= 1)
            d += __shfl_xor_sync(0xffffffffu, d, o);
        if (lane == 0) wden[warp] = d;
    }

    // ---- V accumulation: warp handles tokens s == warp (mod 4)
    float a0=0.f, a1=0.f, a2=0.f, a3=0.f;
    {
        const int4* vp = (const int4*)(v_cache +
            (((size_t)(b*Pn + pageA)*Sn)*HKV + hkv)*Dn) + lane;
        #pragma unroll
        for (int s2 = 0; s2 < 16; s2++) {
            int4 vv = vp[(size_t)(s2*4 + warp) * (HKV*Dn/4)];
            float ww = __shfl_sync(0xffffffffu, wv0, s2);
            a0 += ww*(float)vv.x; a1 += ww*(float)vv.y;
            a2 += ww*(float)vv.z; a3 += ww*(float)vv.w;
        }
    }
    {
        const int4* vp = (const int4*)(v_cache +
            (((size_t)(b*Pn + pageB)*Sn)*HKV + hkv)*Dn) + lane;
        #pragma unroll
        for (int s2 = 0; s2 < 16; s2++) {
            int4 vv = vp[(size_t)(s2*4 + warp) * (HKV*Dn/4)];
            float ww = __shfl_sync(0xffffffffu, wv1, s2);
            a0 += ww*(float)vv.x; a1 += ww*(float)vv.y;
            a2 += ww*(float)vv.z; a3 += ww*(float)vv.w;
        }
    }
    part[warp][lane] = make_float4(a0, a1, a2, a3);
    __syncthreads();

    {
        int lane2 = tid >> 2, comp = tid & 3;
        float acc = 0.f;
        #pragma unroll
        for (int g2 = 0; g2 < 4; g2++) {
            float4 pv = part[g2][lane2];
            acc += (comp==0) ? pv.x : (comp==1) ? pv.y : (comp==2) ? pv.z : pv.w;
        }
        g_part[((size_t)head*8 + j)*Dn + tid] = acc;
    }
    if (tid == 0)
        g_pden[head*8 + j] = (wden[0] + wden[1]) + (wden[2] + wden[3]);

    // arrival counter: last block of this head finalizes (deterministic sum)
    __threadfence();
    __syncthreads();
    if (tid == 0) {
        int old = atomicAdd(&g_cnt[head], 1);
        s_last = (old == 7) ? 1 : 0;
        if (s_last) g_cnt[head] = 0;   // reset for next graph replay
    }
    __syncthreads();
    if (!s_last) return;
    __threadfence();

    float acc = 0.f;
    const float* pp = g_part + (size_t)head*8*Dn + tid;
    #pragma unroll
    for (int jj = 0; jj < 8; jj++) acc += pp[jj*Dn];

    float ecur = __expf(curv - m);
    float den = ecur;
    const float* dp = g_pden + head*8;
    #pragma unroll
    for (int jj = 0; jj < 8; jj++) den += dp[jj];

    float o = acc * kv_scale[1] + ecur * v_cur[(size_t)(b*HKV + hkv)*Dn + tid];
    out[(size_t)head*Dn + tid] = o / den;
}

// ---------------------------------------------------------------- launch
extern "C" void kernel_launch(void* const* d_in, const int* in_sizes, int n_in,
                              void* d_out, int out_size)
{
    const float* q        = (const float*)d_in[0];
    const float* k        = (const float*)d_in[1];
    const float* v        = (const float*)d_in[2];
    const float* kv_scale = (const float*)d_in[3];
    const int*   k_cache  = (const int*)  d_in[4];
    const int*   v_cache  = (const int*)  d_in[5];
    const int*   lengths  = (const int*)  d_in[6];
    const int*   timestep = (const int*)  d_in[7];
    float* out = (float*)d_out;

    int write_idx = (out_size >= Bn*Hn*Dn + Bn*Hn*KP) ? 1 : 0;

    prep_kernel<<<Bn*Hn, 64>>>(q, timestep);
    score_kernel<<<dim3(Pn, Bn*HKV), 256>>>(k_cache, kv_scale, lengths);
    attn_kernel<<<Bn*Hn*8, 128>>>(q, k, v_cache, v, kv_scale, out,
                                  out + Bn*Hn*Dn, write_idx);
}